// round 1
// baseline (speedup 1.0000x reference)
#include <cuda_runtime.h>

#define BATCH   8
#define NPTS    4096
#define THREADS 128
#define PTS     4                       // query points per thread
#define PTS_BLK (THREADS * PTS)         // 512
#define XT      (NPTS / PTS_BLK)        // 8 query tiles
#define NC      4                       // reference chunks
#define CH      (NPTS / NC)             // 1024 reference pts per chunk

// Scratch (allocation-free contract): partial mins + per-(dir,batch) sums.
__device__ float g_pmin[2 * BATCH * NC * NPTS];   // 1 MB
__device__ float g_psum[2 * BATCH];

// Main all-pairs kernel.
// For each (dir, b, query-tile, ref-chunk): compute per-query
//   min over chunk of (yy - 2 * x.y), i.e. distance minus the hoisted xx term.
__global__ void __launch_bounds__(THREADS)
chamfer_main(const float* __restrict__ X, const float* __restrict__ Y) {
    __shared__ float4 sq[CH];   // (q0, q1, q2, q0^2+q1^2+q2^2)

    int bid = blockIdx.x;
    int c   = bid & (NC - 1);  bid >>= 2;
    int xt  = bid & (XT - 1);  bid >>= 3;
    int b   = bid & (BATCH-1); bid >>= 3;
    int dir = bid;                        // 0: x->y, 1: y->x

    const float* P = dir ? Y : X;         // query set
    const float* Q = dir ? X : Y;         // reference set
    const float* Qb = Q + b * 3 * NPTS;
    const float* Pb = P + b * 3 * NPTS;

    int tid = threadIdx.x;

    // Stage reference chunk into smem (coalesced per-dim loads).
    for (int m = tid; m < CH; m += THREADS) {
        int gm  = c * CH + m;
        float q0 = Qb[gm];
        float q1 = Qb[gm + NPTS];
        float q2 = Qb[gm + 2 * NPTS];
        sq[m] = make_float4(q0, q1, q2, q0*q0 + q1*q1 + q2*q2);
    }
    __syncthreads();

    // Load 4 query points per thread; pre-scale by -2 so inner op is 3 FFMA.
    float a0[PTS], a1[PTS], a2[PTS], mn[PTS];
    #pragma unroll
    for (int k = 0; k < PTS; k++) {
        int n = xt * PTS_BLK + k * THREADS + tid;
        a0[k] = -2.0f * Pb[n];
        a1[k] = -2.0f * Pb[n + NPTS];
        a2[k] = -2.0f * Pb[n + 2 * NPTS];
        mn[k] = 3.0e38f;
    }

    // Inner loop: 1 broadcast LDS.128 + 12 FFMA + 4 FMNMX per thread-iter.
    #pragma unroll 4
    for (int j = 0; j < CH; j++) {
        float4 q = sq[j];
        #pragma unroll
        for (int k = 0; k < PTS; k++) {
            float t = fmaf(a0[k], q.x, fmaf(a1[k], q.y, fmaf(a2[k], q.z, q.w)));
            mn[k] = fminf(mn[k], t);
        }
    }

    float* out = g_pmin + ((dir * BATCH + b) * NC + c) * NPTS;
    #pragma unroll
    for (int k = 0; k < PTS; k++)
        out[xt * PTS_BLK + k * THREADS + tid] = mn[k];
}

// Per-(dir, batch) reduction: min over chunks, add back xx, sum over points.
__global__ void __launch_bounds__(256)
chamfer_reduce(const float* __restrict__ X, const float* __restrict__ Y) {
    int db  = blockIdx.x;          // 0..15
    int dir = db >> 3;
    int b   = db & 7;
    const float* P  = dir ? Y : X;
    const float* Pb = P + b * 3 * NPTS;
    const float* pm = g_pmin + db * NC * NPTS;

    float s = 0.0f;
    for (int n = threadIdx.x; n < NPTS; n += 256) {
        float v = pm[n];
        #pragma unroll
        for (int c = 1; c < NC; c++) v = fminf(v, pm[c * NPTS + n]);
        float p0 = Pb[n], p1 = Pb[n + NPTS], p2 = Pb[n + 2 * NPTS];
        s += v + p0*p0 + p1*p1 + p2*p2;
    }

    __shared__ float red[256];
    red[threadIdx.x] = s;
    __syncthreads();
    for (int st = 128; st > 0; st >>= 1) {
        if (threadIdx.x < st) red[threadIdx.x] += red[threadIdx.x + st];
        __syncthreads();
    }
    if (threadIdx.x == 0) g_psum[db] = red[0];
}

// Finalize: mean over batches of (Ls1s2 + Ls2s1).
__global__ void chamfer_final(float* __restrict__ out) {
    float s = (threadIdx.x < 2 * BATCH) ? g_psum[threadIdx.x] : 0.0f;
    #pragma unroll
    for (int off = 16; off > 0; off >>= 1)
        s += __shfl_down_sync(0xffffffff, s, off);
    if (threadIdx.x == 0)
        out[0] = s / (float)(NPTS * BATCH);
}

extern "C" void kernel_launch(void* const* d_in, const int* in_sizes, int n_in,
                              void* d_out, int out_size) {
    const float* x = (const float*)d_in[0];
    const float* y = (const float*)d_in[1];
    float* out = (float*)d_out;

    chamfer_main<<<2 * BATCH * XT * NC, THREADS>>>(x, y);
    chamfer_reduce<<<2 * BATCH, 256>>>(x, y);
    chamfer_final<<<1, 32>>>(out);
}

// round 3
// speedup vs baseline: 1.1314x; 1.1314x over previous
#include <cuda_runtime.h>

#define BATCH   8
#define NPTS    4096
#define THREADS 128
#define PTS     8                        // query points per thread (4 packed pairs)
#define NPAIR   (PTS / 2)
#define PTS_BLK (THREADS * PTS)          // 1024
#define XT      (NPTS / PTS_BLK)         // 4 query tiles
#define NC      16                       // reference chunks
#define CH      (NPTS / NC)              // 256 reference pts per chunk
#define RSLICE  8                        // reduction blocks per (dir,b)

// Scratch (allocation-free contract).
__device__ float g_pmin[2 * BATCH * NC * NPTS];        // 8 MB partial mins
__device__ float g_psum[2 * BATCH * RSLICE];           // 128 partial sums

// ---- packed f32x2 helpers -------------------------------------------------
__device__ __forceinline__ unsigned long long fma2(unsigned long long a,
                                                   unsigned long long b,
                                                   unsigned long long c) {
    unsigned long long d;
    asm("fma.rn.f32x2 %0, %1, %2, %3;" : "=l"(d) : "l"(a), "l"(b), "l"(c));
    return d;
}
__device__ __forceinline__ unsigned long long pack2(float lo, float hi) {
    unsigned long long v;
    asm("mov.b64 %0, {%1, %2};" : "=l"(v) : "f"(lo), "f"(hi));
    return v;
}
__device__ __forceinline__ float2 unpack2(unsigned long long v) {
    float2 r;
    asm("mov.b64 {%0, %1}, %2;" : "=f"(r.x), "=f"(r.y) : "l"(v));
    return r;
}

// ---- main all-pairs kernel ------------------------------------------------
// For each (dir, b, query-tile, ref-chunk): per-query min over chunk of
// (qq - 2*p.q); the p.p term is hoisted and re-added in the reduction.
__global__ void __launch_bounds__(THREADS)
chamfer_main(const float* __restrict__ X, const float* __restrict__ Y) {
    // Pre-duplicated reference layout: per point, 32 bytes:
    //   float4 #0 = (q0,q0, q1,q1), float4 #1 = (q2,q2, qq,qq)
    __shared__ float4 sq[CH * 2];

    int bid = blockIdx.x;
    int c   = bid & (NC - 1);   bid >>= 4;
    int xt  = bid & (XT - 1);   bid >>= 2;
    int b   = bid & (BATCH-1);  bid >>= 3;
    int dir = bid;                        // 0: x->y, 1: y->x

    const float* P  = dir ? Y : X;        // query set
    const float* Q  = dir ? X : Y;        // reference set
    const float* Qb = Q + b * 3 * NPTS;
    const float* Pb = P + b * 3 * NPTS;

    int tid = threadIdx.x;

    // Stage reference chunk (duplicated lanes for f32x2 broadcast).
    for (int m = tid; m < CH; m += THREADS) {
        int gm   = c * CH + m;
        float q0 = Qb[gm];
        float q1 = Qb[gm + NPTS];
        float q2 = Qb[gm + 2 * NPTS];
        float qq = q0*q0 + q1*q1 + q2*q2;
        sq[m * 2 + 0] = make_float4(q0, q0, q1, q1);
        sq[m * 2 + 1] = make_float4(q2, q2, qq, qq);
    }
    __syncthreads();

    // 4 packed query pairs per thread, coefficients pre-scaled by -2.
    unsigned long long pa0[NPAIR], pa1[NPAIR], pa2[NPAIR];
    float mn[PTS];
    #pragma unroll
    for (int p = 0; p < NPAIR; p++) {
        int n0 = xt * PTS_BLK + (2*p)   * THREADS + tid;
        int n1 = xt * PTS_BLK + (2*p+1) * THREADS + tid;
        pa0[p] = pack2(-2.0f * Pb[n0],            -2.0f * Pb[n1]);
        pa1[p] = pack2(-2.0f * Pb[n0 + NPTS],     -2.0f * Pb[n1 + NPTS]);
        pa2[p] = pack2(-2.0f * Pb[n0 + 2*NPTS],   -2.0f * Pb[n1 + 2*NPTS]);
        mn[2*p] = 3.0e38f; mn[2*p+1] = 3.0e38f;
    }

    // Inner loop: 2 broadcast LDS.128 + 12 FFMA2 + 8 FMNMX per 8 pairs/thread.
    const ulonglong2* s2 = reinterpret_cast<const ulonglong2*>(sq);
    #pragma unroll 4
    for (int j = 0; j < CH; j++) {
        ulonglong2 A = s2[2*j];       // A.x={q0,q0}  A.y={q1,q1}
        ulonglong2 B = s2[2*j + 1];   // B.x={q2,q2}  B.y={qq,qq}
        #pragma unroll
        for (int p = 0; p < NPAIR; p++) {
            unsigned long long t =
                fma2(pa0[p], A.x, fma2(pa1[p], A.y, fma2(pa2[p], B.x, B.y)));
            float2 tf = unpack2(t);
            mn[2*p]   = fminf(mn[2*p],   tf.x);
            mn[2*p+1] = fminf(mn[2*p+1], tf.y);
        }
    }

    float* out = g_pmin + ((dir * BATCH + b) * NC + c) * NPTS;
    #pragma unroll
    for (int k = 0; k < PTS; k++)
        out[xt * PTS_BLK + k * THREADS + tid] = mn[k];
}

// ---- reduction: min over chunks, add back hoisted |p|^2, partial sums -----
__global__ void __launch_bounds__(256)
chamfer_reduce(const float* __restrict__ X, const float* __restrict__ Y) {
    int db  = blockIdx.x / RSLICE;        // 0..15  (dir*8 + b)
    int s   = blockIdx.x % RSLICE;
    int dir = db >> 3;
    int b   = db & 7;
    const float* P  = dir ? Y : X;
    const float* Pb = P + b * 3 * NPTS;
    const float* pm = g_pmin + db * NC * NPTS;

    const int SLICE = NPTS / RSLICE;      // 512
    float acc = 0.0f;
    for (int n = s * SLICE + threadIdx.x; n < (s + 1) * SLICE; n += 256) {
        float v = pm[n];
        #pragma unroll
        for (int c = 1; c < NC; c++) v = fminf(v, pm[c * NPTS + n]);
        float p0 = Pb[n], p1 = Pb[n + NPTS], p2 = Pb[n + 2 * NPTS];
        acc += v + p0*p0 + p1*p1 + p2*p2;
    }

    __shared__ float red[256];
    red[threadIdx.x] = acc;
    __syncthreads();
    for (int st = 128; st > 0; st >>= 1) {
        if (threadIdx.x < st) red[threadIdx.x] += red[threadIdx.x + st];
        __syncthreads();
    }
    if (threadIdx.x == 0) g_psum[blockIdx.x] = red[0];
}

// ---- finalize: sum 128 partials, mean over batches ------------------------
__global__ void __launch_bounds__(128)
chamfer_final(float* __restrict__ out) {
    __shared__ float red[128];
    red[threadIdx.x] = g_psum[threadIdx.x];
    __syncthreads();
    for (int st = 64; st > 0; st >>= 1) {
        if (threadIdx.x < st) red[threadIdx.x] += red[threadIdx.x + st];
        __syncthreads();
    }
    if (threadIdx.x == 0)
        out[0] = red[0] / (float)(NPTS * BATCH);
}

extern "C" void kernel_launch(void* const* d_in, const int* in_sizes, int n_in,
                              void* d_out, int out_size) {
    const float* x = (const float*)d_in[0];
    const float* y = (const float*)d_in[1];
    float* out = (float*)d_out;

    chamfer_main<<<2 * BATCH * XT * NC, THREADS>>>(x, y);
    chamfer_reduce<<<2 * BATCH * RSLICE, 256>>>(x, y);
    chamfer_final<<<1, 128>>>(out);
}

// round 6
// speedup vs baseline: 1.1898x; 1.0516x over previous
#include <cuda_runtime.h>

#define BATCH   8
#define NPTS    4096
#define THREADS 128
#define PTS     8                        // query points per thread (4 packed pairs)
#define NPAIR   (PTS / 2)
#define PTS_BLK (THREADS * PTS)          // 1024
#define XT      (NPTS / PTS_BLK)         // 4 query tiles
#define NC      32                       // reference chunks
#define CH      (NPTS / NC)              // 128 reference pts per chunk
#define RSLICE  8                        // reduction blocks per (dir,b)
#define RBLKS   (2 * BATCH * RSLICE)     // 128

// Scratch (allocation-free contract).
__device__ float g_pmin[2 * BATCH * NC * NPTS];        // 8.4 MB partial mins
__device__ float g_psum[RBLKS];                        // 128 partial sums
__device__ int   g_ctr = 0;                            // last-block counter

// ---- packed f32x2 helpers -------------------------------------------------
__device__ __forceinline__ unsigned long long fma2(unsigned long long a,
                                                   unsigned long long b,
                                                   unsigned long long c) {
    unsigned long long d;
    asm("fma.rn.f32x2 %0, %1, %2, %3;" : "=l"(d) : "l"(a), "l"(b), "l"(c));
    return d;
}
__device__ __forceinline__ unsigned long long pack2(float lo, float hi) {
    unsigned long long v;
    asm("mov.b64 %0, {%1, %2};" : "=l"(v) : "f"(lo), "f"(hi));
    return v;
}
__device__ __forceinline__ float2 unpack2(unsigned long long v) {
    float2 r;
    asm("mov.b64 {%0, %1}, %2;" : "=f"(r.x), "=f"(r.y) : "l"(v));
    return r;
}

// ---- main all-pairs kernel ------------------------------------------------
// For each (dir, b, query-tile, ref-chunk): per-query min over chunk of
// (qq - 2*p.q); the p.p term is hoisted and re-added in the reduction.
__global__ void __launch_bounds__(THREADS)
chamfer_main(const float* __restrict__ X, const float* __restrict__ Y) {
    // Pre-duplicated reference layout, 32 B/point:
    //   float4 #0 = (q0,q0, q1,q1), float4 #1 = (q2,q2, qq,qq)
    __shared__ float4 sq[CH * 2];

    int bid = blockIdx.x;
    int c   = bid & (NC - 1);   bid >>= 5;
    int xt  = bid & (XT - 1);   bid >>= 2;
    int b   = bid & (BATCH-1);  bid >>= 3;
    int dir = bid;                        // 0: x->y, 1: y->x

    const float* P  = dir ? Y : X;        // query set
    const float* Q  = dir ? X : Y;        // reference set
    const float* Qb = Q + b * 3 * NPTS;
    const float* Pb = P + b * 3 * NPTS;

    int tid = threadIdx.x;

    // Stage reference chunk (duplicated lanes for f32x2 broadcast).
    if (tid < CH) {
        int gm   = c * CH + tid;
        float q0 = Qb[gm];
        float q1 = Qb[gm + NPTS];
        float q2 = Qb[gm + 2 * NPTS];
        float qq = q0*q0 + q1*q1 + q2*q2;
        sq[tid * 2 + 0] = make_float4(q0, q0, q1, q1);
        sq[tid * 2 + 1] = make_float4(q2, q2, qq, qq);
    }
    __syncthreads();

    // 4 packed query pairs per thread, coefficients pre-scaled by -2.
    unsigned long long pa0[NPAIR], pa1[NPAIR], pa2[NPAIR];
    float mn[PTS];
    #pragma unroll
    for (int p = 0; p < NPAIR; p++) {
        int n0 = xt * PTS_BLK + (2*p)   * THREADS + tid;
        int n1 = xt * PTS_BLK + (2*p+1) * THREADS + tid;
        pa0[p] = pack2(-2.0f * Pb[n0],            -2.0f * Pb[n1]);
        pa1[p] = pack2(-2.0f * Pb[n0 + NPTS],     -2.0f * Pb[n1 + NPTS]);
        pa2[p] = pack2(-2.0f * Pb[n0 + 2*NPTS],   -2.0f * Pb[n1 + 2*NPTS]);
        mn[2*p] = 3.0e38f; mn[2*p+1] = 3.0e38f;
    }

    // Inner loop: 2 broadcast LDS.128 + 12 FFMA2 + 8 FMNMX per 8 pairs/thread.
    const ulonglong2* s2 = reinterpret_cast<const ulonglong2*>(sq);
    #pragma unroll 4
    for (int j = 0; j < CH; j++) {
        ulonglong2 A = s2[2*j];       // A.x={q0,q0}  A.y={q1,q1}
        ulonglong2 B = s2[2*j + 1];   // B.x={q2,q2}  B.y={qq,qq}
        #pragma unroll
        for (int p = 0; p < NPAIR; p++) {
            unsigned long long t =
                fma2(pa0[p], A.x, fma2(pa1[p], A.y, fma2(pa2[p], B.x, B.y)));
            float2 tf = unpack2(t);
            mn[2*p]   = fminf(mn[2*p],   tf.x);
            mn[2*p+1] = fminf(mn[2*p+1], tf.y);
        }
    }

    float* out = g_pmin + ((dir * BATCH + b) * NC + c) * NPTS;
    #pragma unroll
    for (int k = 0; k < PTS; k++)
        out[xt * PTS_BLK + k * THREADS + tid] = mn[k];
}

// ---- fused reduction + finalize -------------------------------------------
// Per block: min over chunks, add back hoisted |p|^2, partial-sum a slice.
// Last block to finish sums the 128 partials and writes the scalar mean.
__global__ void __launch_bounds__(256)
chamfer_reduce(const float* __restrict__ X, const float* __restrict__ Y,
               float* __restrict__ out) {
    int db  = blockIdx.x / RSLICE;        // 0..15  (dir*8 + b)
    int s   = blockIdx.x % RSLICE;
    int dir = db >> 3;
    int b   = db & 7;
    const float* P  = dir ? Y : X;
    const float* Pb = P + b * 3 * NPTS;
    const float* pm = g_pmin + db * NC * NPTS;

    const int SLICE = NPTS / RSLICE;      // 512
    float acc = 0.0f;
    for (int n = s * SLICE + threadIdx.x; n < (s + 1) * SLICE; n += 256) {
        float v = pm[n];
        #pragma unroll
        for (int c = 1; c < NC; c++) v = fminf(v, pm[c * NPTS + n]);
        float p0 = Pb[n], p1 = Pb[n + NPTS], p2 = Pb[n + 2 * NPTS];
        acc += v + p0*p0 + p1*p1 + p2*p2;
    }

    __shared__ float red[256];
    __shared__ bool  is_last;
    red[threadIdx.x] = acc;
    __syncthreads();
    for (int st = 128; st > 0; st >>= 1) {
        if (threadIdx.x < st) red[threadIdx.x] += red[threadIdx.x + st];
        __syncthreads();
    }
    if (threadIdx.x == 0) {
        g_psum[blockIdx.x] = red[0];
        __threadfence();
        int prev = atomicAdd(&g_ctr, 1);
        is_last = (prev == RBLKS - 1);
    }
    __syncthreads();

    if (is_last) {
        // Deterministic finalize: one block sums the fixed 128-entry array.
        float v = 0.0f;
        if (threadIdx.x < RBLKS)
            v = *((volatile float*)&g_psum[threadIdx.x]);
        red[threadIdx.x] = v;
        __syncthreads();
        for (int st = 128; st > 0; st >>= 1) {
            if (threadIdx.x < st) red[threadIdx.x] += red[threadIdx.x + st];
            __syncthreads();
        }
        if (threadIdx.x == 0) {
            out[0] = red[0] / (float)(NPTS * BATCH);
            g_ctr = 0;                    // reset for next graph replay
        }
    }
}

extern "C" void kernel_launch(void* const* d_in, const int* in_sizes, int n_in,
                              void* d_out, int out_size) {
    const float* x = (const float*)d_in[0];
    const float* y = (const float*)d_in[1];
    float* out = (float*)d_out;

    chamfer_main<<<2 * BATCH * XT * NC, THREADS>>>(x, y);
    chamfer_reduce<<<RBLKS, 256>>>(x, y, out);
}